// round 10
// baseline (speedup 1.0000x reference)
#include <cuda_runtime.h>
#include <math.h>

#define LL 3136
#define NB 16

// ---------------- scratch ----------------
__device__ float g_y[(size_t)NB*128*LL];
__device__ float g_xin[(size_t)NB*128*LL];
__device__ float g_xconv[(size_t)NB*128*LL];
__device__ float g_xconvT[(size_t)NB*128*LL];
__device__ float g_yg[(size_t)NB*128*LL];
__device__ float g_xres[(size_t)NB*128*LL];
__device__ float g_delta[(size_t)NB*4*128*LL];
__device__ float g_ys[(size_t)NB*4*128*LL];
__device__ float g_Bc[(size_t)NB*4*LL*16];
__device__ float g_Cc[(size_t)NB*4*LL*16];
__device__ float g_p[2048];
__device__ float g_s[2048];

__device__ __forceinline__ float gelu_t(float x){
    float a = 1.5957691216057308f*(x + 0.044715f*x*x*x);
    return x / (1.f + __expf(-a));
}

// ======== K1: window attention (1024 windows, 256 thr) ========
__global__ void k_attn(const float* __restrict__ x,
    const float* __restrict__ wq, const float* __restrict__ wk, const float* __restrict__ wv,
    const float* __restrict__ wp, const float* __restrict__ bp,
    const float* __restrict__ gq, const float* __restrict__ gk, const float* __restrict__ gv)
{
    extern __shared__ float sm[];
    float* xs  = sm;             // 49*65
    float* qs  = xs + 3185;
    float* ks  = qs + 3185;
    float* vs  = ks + 3185;
    float* wb  = vs + 3185;      // 64*65 (also scores 49*49)
    float* inv = wb + 4160;      // 64
    int tid = threadIdx.x;
    int wi = blockIdx.x;
    int b = wi >> 6, wy = (wi >> 3) & 7, wx = wi & 7;
    const float* xb = x + (size_t)b*128*LL;
    for (int i = tid; i < 49*64; i += 256){
        int c = i / 49, t = i % 49;
        xs[t*65+c] = xb[(size_t)c*LL + (wy*7 + t/7)*56 + wx*7 + t%7];
    }
    __syncthreads();
    if (tid < 49){
        float v = 0.f;
        for (int c=0;c<64;c++){ float a = xs[tid*65+c]; v += a*a; }
        inv[tid] = rsqrtf(v*(1.f/64.f) + 1e-5f);
    }
    __syncthreads();
    const float* Wm[3] = {wq,wk,wv};
    const float* Gm[3] = {gq,gk,gv};
    float* Dst[3] = {qs,ks,vs};
    for (int m=0;m<3;m++){
        for (int i = tid; i < 64*64; i += 256){
            int o = i >> 6, c = i & 63;
            wb[o*65+c] = Wm[m][o*64+c]*Gm[m][c];
        }
        __syncthreads();
        for (int i = tid; i < 49*64; i += 256){
            int t = i >> 6, o = i & 63;
            float acc = 0.f;
            #pragma unroll 8
            for (int c=0;c<64;c++) acc += xs[t*65+c]*wb[o*65+c];
            Dst[m][t*65+o] = acc*inv[t];
        }
        __syncthreads();
    }
    float* ss = wb;
    float* os = xs;  // overwrite xs with attention output
    const float scale = 0.3535533905932738f;
    for (int hh=0; hh<8; hh++){
        for (int i=tid; i<49*49; i+=256){
            int t = i/49, u = i%49;
            float acc=0.f;
            #pragma unroll
            for(int j=0;j<8;j++) acc += qs[t*65+hh*8+j]*ks[u*65+hh*8+j];
            ss[t*49+u] = acc*scale;
        }
        __syncthreads();
        if (tid < 49){
            float mx = -1e30f;
            for(int u=0;u<49;u++) mx = fmaxf(mx, ss[tid*49+u]);
            float sum=0.f;
            for(int u=0;u<49;u++){ float e=__expf(ss[tid*49+u]-mx); ss[tid*49+u]=e; sum+=e; }
            float r = 1.f/sum;
            for(int u=0;u<49;u++) ss[tid*49+u]*=r;
        }
        __syncthreads();
        for (int i=tid; i<49*8; i+=256){
            int t = i>>3, j = i&7;
            float acc=0.f;
            for(int u=0;u<49;u++) acc += ss[t*49+u]*vs[u*65+hh*8+j];
            os[t*65+hh*8+j] = acc;
        }
        __syncthreads();
    }
    for (int i=tid;i<64*64;i+=256){ int o=i>>6,c=i&63; wb[o*65+c]=wp[o*64+c]; }
    __syncthreads();
    for (int i=tid;i<49*64;i+=256){
        int o = i/49, t = i%49;
        float acc = bp[o];
        #pragma unroll 8
        for(int c=0;c<64;c++) acc += os[t*65+c]*wb[o*65+c];
        g_y[((size_t)b*128+o)*LL + (wy*7 + t/7)*56 + wx*7 + t%7] = acc;
    }
}

// ======== K2a: rms2d + in-proj 64->128 ========
__global__ void k_rms_in(const float* __restrict__ x, const float* __restrict__ min_w,
                         const float* __restrict__ gvm)
{
    extern __shared__ float sm[];
    float* xt  = sm;            // [64][64]
    float* ws  = xt + 4096;     // [128][64]
    float* inv = ws + 8192;     // 64
    int tid = threadIdx.x;
    int b = blockIdx.x / 49, l0 = (blockIdx.x % 49)*64;
    const float* x2 = x + ((size_t)b*128 + 64)*LL;
    for (int i=tid;i<4096;i+=256){ int c=i>>6,p=i&63; xt[i] = x2[(size_t)c*LL + l0+p]; }
    for (int i=tid;i<8192;i+=256){ int c=i&63; ws[i] = min_w[i]*gvm[c]; }
    __syncthreads();
    if (tid<64){ float v=0.f;
        #pragma unroll 8
        for(int c=0;c<64;c++){float a=xt[c*64+tid]; v+=a*a;}
        inv[tid]=rsqrtf(v*(1.f/64.f)+1e-5f); }
    __syncthreads();
    for (int i=tid;i<8192;i+=256){
        int d=i>>6,p=i&63;
        float acc=0.f;
        #pragma unroll 8
        for(int c=0;c<64;c++) acc += ws[d*64+c]*xt[c*64+p];
        g_xin[((size_t)b*128+d)*LL + l0+p] = acc*inv[p];
    }
}

// ======== K2b: depthwise 3x3 + bias + silu ========
__global__ void k_dwconv(const float* __restrict__ cw, const float* __restrict__ cb)
{
    __shared__ float t[58*58];
    int bd = blockIdx.x, d = bd & 127, tid = threadIdx.x;
    const float* src = g_xin + (size_t)bd*LL;
    for (int i=tid;i<58*58;i+=256){
        int hh = i/58 - 1, ww = i%58 - 1;
        t[i] = (hh>=0 && hh<56 && ww>=0 && ww<56) ? src[hh*56+ww] : 0.f;
    }
    float w9[9];
    #pragma unroll
    for(int j=0;j<9;j++) w9[j] = cw[d*9+j];
    float bias = cb[d];
    __syncthreads();
    float* dst = g_xconv + (size_t)bd*LL;
    for (int i=tid;i<LL;i+=256){
        const float* tp = t + (i/56)*58 + i%56;
        float a = bias;
        #pragma unroll
        for(int dy=0;dy<3;dy++)
            #pragma unroll
            for(int dx=0;dx<3;dx++) a += w9[dy*3+dx]*tp[dy*58+dx];
        dst[i] = a / (1.f + __expf(-a));
    }
}

// ======== K2c: per-plane transpose ========
__global__ void k_transpose(){
    __shared__ float t[56*57];
    int bd = blockIdx.x, tid = threadIdx.x;
    const float* src = g_xconv + (size_t)bd*LL;
    float* dst = g_xconvT + (size_t)bd*LL;
    for(int i=tid;i<LL;i+=256) t[(i/56)*57 + i%56] = src[i];
    __syncthreads();
    for(int j=tid;j<LL;j+=256) dst[j] = t[(j%56)*57 + j/56];
}

// ======== K3: xproj + dt + softplus -> delta/B/C (scan order) ========
__global__ void k_xproj(const float* __restrict__ xproj, const float* __restrict__ dtw,
                        const float* __restrict__ dtb)
{
    extern __shared__ float sm[];
    float* xt    = sm;              // [128][64]
    float* wp_   = xt + 8192;       // [128][36]
    float* xd    = wp_ + 4608;      // [36][65]
    float* dtw_s = xd + 2340;       // 512
    float* dtb_s = dtw_s + 512;     // 128
    int tid = threadIdx.x, blk = blockIdx.x;
    int b = blk / 196, r = blk % 196, k = r / 49, l0 = (r%49)*64;
    const float* src = ((k&1)? g_xconvT : g_xconv) + (size_t)b*128*LL;
    bool rev = k >= 2;
    for (int i=tid;i<8192;i+=256){
        int d=i>>6,p=i&63;
        int pos = rev ? (LL-1-(l0+p)) : (l0+p);
        xt[i] = src[(size_t)d*LL + pos];
    }
    for (int i=tid;i<4608;i+=256) wp_[i] = xproj[(size_t)k*4608 + i];
    for (int i=tid;i<512;i+=256) dtw_s[i] = dtw[k*512+i];
    if (tid<128) dtb_s[tid] = dtb[k*128+tid];
    __syncthreads();
    for (int i=tid;i<36*64;i+=256){
        int c = i>>6, p = i&63;
        float acc=0.f;
        #pragma unroll 8
        for(int d=0;d<128;d++) acc += xt[d*64+p]*wp_[d*36+c];
        xd[c*65+p] = acc;
    }
    __syncthreads();
    size_t dbase = ((size_t)(b*4 + k)*128)*LL;
    for (int i=tid;i<8192;i+=256){
        int d=i>>6,p=i&63;
        float a = dtb_s[d];
        #pragma unroll
        for(int rr=0;rr<4;rr++) a += xd[rr*65+p]*dtw_s[d*4+rr];
        float sp = (a > 20.f) ? a : log1pf(__expf(a));
        g_delta[dbase + (size_t)d*LL + l0 + p] = sp;
    }
    size_t bcbase = ((size_t)(b*4+k)*LL + l0)*16;
    for (int i=tid;i<1024;i+=256){
        int p = i>>4, n = i&15;
        g_Bc[bcbase + (size_t)p*16 + n] = xd[(4+n)*65+p];
        g_Cc[bcbase + (size_t)p*16 + n] = xd[(20+n)*65+p];
    }
}

// ======== K4: selective scan (8 states/lane, 2 lanes/seq) ========
__global__ void __launch_bounds__(128) k_scan(const float* __restrict__ Alog,
                                              const float* __restrict__ Dp)
{
    int blk = blockIdx.x;                 // 128 blocks
    int b = blk >> 3, k = (blk>>1)&3, half = blk&1;
    int wid = threadIdx.x >> 5, lane = threadIdx.x & 31;
    int s = lane >> 1, sub = lane & 1;
    int d = half*64 + wid*16 + s;
    size_t seq = (size_t)(b*4+k)*128 + d;
    const float* dptr = g_delta + seq*LL;
    const float* uptr = ((k&1)? g_xconvT : g_xconv) + ((size_t)b*128 + d)*LL;
    float* yptr = g_ys + seq*LL;
    bool rev = k>=2;
    float A[8];
    #pragma unroll
    for(int j=0;j<8;j++) A[j] = -__expf(__ldg(Alog + ((size_t)k*128+d)*16 + sub*8 + j));
    float Dv = __ldg(Dp + k*128 + d);
    const float4* B4 = (const float4*)(g_Bc + (size_t)(b*4+k)*LL*16) + sub*2;
    const float4* C4 = (const float4*)(g_Cc + (size_t)(b*4+k)*LL*16) + sub*2;
    float h0=0,h1=0,h2=0,h3=0,h4=0,h5=0,h6=0,h7=0;
    for (int t=0;t<LL;t++){
        int pos = rev ? (LL-1-t) : t;
        float dl = __ldg(dptr + t);
        float u  = __ldg(uptr + pos);
        float4 ba = __ldg(B4 + (size_t)t*4);
        float4 bb = __ldg(B4 + (size_t)t*4 + 1);
        float4 ca = __ldg(C4 + (size_t)t*4);
        float4 cb = __ldg(C4 + (size_t)t*4 + 1);
        float du = dl*u, y;
        h0 = __expf(dl*A[0])*h0 + du*ba.x; y  = h0*ca.x;
        h1 = __expf(dl*A[1])*h1 + du*ba.y; y += h1*ca.y;
        h2 = __expf(dl*A[2])*h2 + du*ba.z; y += h2*ca.z;
        h3 = __expf(dl*A[3])*h3 + du*ba.w; y += h3*ca.w;
        h4 = __expf(dl*A[4])*h4 + du*bb.x; y += h4*cb.x;
        h5 = __expf(dl*A[5])*h5 + du*bb.y; y += h5*cb.y;
        h6 = __expf(dl*A[6])*h6 + du*bb.z; y += h6*cb.z;
        h7 = __expf(dl*A[7])*h7 + du*bb.w; y += h7*cb.w;
        y += __shfl_xor_sync(0xffffffffu, y, 1);
        if (sub == 0) yptr[pos] = y + Dv*u;
    }
}

// ======== K4b: cross-merge + gelu ========
__global__ void k_merge(){
    __shared__ float t[56*57];
    int bd = blockIdx.x, b = bd >> 7, d = bd & 127, tid = threadIdx.x;
    size_t base = ((size_t)b*4)*128*LL + (size_t)d*LL;
    const float* y0 = g_ys + base;
    const float* y1 = g_ys + base + (size_t)128*LL;
    const float* y2 = g_ys + base + (size_t)2*128*LL;
    const float* y3 = g_ys + base + (size_t)3*128*LL;
    for (int j=tid;j<LL;j+=256) t[(j/56)*57 + j%56] = y1[j] + y3[j];
    __syncthreads();
    float* dst = g_yg + ((size_t)b*128 + d)*LL;
    for (int i=tid;i<LL;i+=256){
        float v = y0[i] + y2[i] + t[(i%56)*57 + i/56];
        dst[i] = gelu_t(v);
    }
}

// ======== K5: out-proj 128->64 -> g_y channels 64..127 ========
__global__ void k_outproj(const float* __restrict__ ow){
    extern __shared__ float sm[];
    float* ws = sm;            // [64][128]
    float* yt = ws + 8192;     // [128][64]
    int tid=threadIdx.x;
    int b = blockIdx.x/49, l0=(blockIdx.x%49)*64;
    for (int i=tid;i<8192;i+=256) ws[i]=ow[i];
    const float* src = g_yg + (size_t)b*128*LL;
    for (int i=tid;i<8192;i+=256){ int d=i>>6,p=i&63; yt[i]=src[(size_t)d*LL+l0+p]; }
    __syncthreads();
    for (int i=tid;i<4096;i+=256){
        int o=i>>6, p=i&63;
        float acc=0.f;
        #pragma unroll 8
        for(int d=0;d<128;d++) acc += ws[o*128+d]*yt[d*64+p];
        g_y[((size_t)b*128 + 64 + o)*LL + l0+p] = acc;
    }
}

// ======== K6: SE pool / gate / residual ========
__global__ void k_pool(){
    __shared__ float red[256];
    int bc = blockIdx.x, tid = threadIdx.x;
    const float* src = g_y + (size_t)bc*LL;
    float s=0.f;
    for(int i=tid;i<LL;i+=256) s += src[i];
    red[tid]=s; __syncthreads();
    for(int o=128;o>0;o>>=1){ if(tid<o) red[tid]+=red[tid+o]; __syncthreads(); }
    if(tid==0) g_p[bc] = red[0]*(1.f/LL);
}
__global__ void k_se(const float* __restrict__ w1, const float* __restrict__ b1,
                     const float* __restrict__ w2, const float* __restrict__ b2){
    __shared__ float p[128], hid[32];
    int b = blockIdx.x, tid = threadIdx.x;
    if (tid<128) p[tid] = g_p[b*128+tid];
    __syncthreads();
    if (tid<32){
        float a = b1[tid];
        #pragma unroll 8
        for(int c=0;c<128;c++) a += w1[tid*128+c]*p[c];
        hid[tid] = fmaxf(a, 0.f);
    }
    __syncthreads();
    if (tid<128){
        float a = b2[tid];
        #pragma unroll
        for(int j=0;j<32;j++) a += w2[tid*32+j]*hid[j];
        g_s[b*128+tid] = 1.f/(1.f+__expf(-a));
    }
}
__global__ void k_resid(const float* __restrict__ x, const float* __restrict__ gamma1){
    size_t i = (size_t)blockIdx.x*256 + threadIdx.x;
    if (i >= (size_t)NB*128*LL) return;
    int bc = (int)(i / LL);
    int c = bc & 127;
    g_xres[i] = x[i] + gamma1[c]*g_s[bc]*g_y[i];
}

// ======== K7: fused RMS + MLP(128->512->128) + residual -> d_out ========
__global__ void __launch_bounds__(256) k_mlp(
    const float* __restrict__ gmlp,
    const float* __restrict__ w1, const float* __restrict__ b1,
    const float* __restrict__ w2, const float* __restrict__ b2,
    const float* __restrict__ gamma2, float* __restrict__ out)
{
    extern __shared__ float sm[];
    float* xt   = sm;            // [128][64] raw xres
    float* h    = xt + 8192;     // [64][68]
    float* wc   = h + 64*68;     // max(8192 w1-chunk, 64*133 w2-chunk)
    float* invp = wc + 8512;     // 64
    int tid = threadIdx.x;
    int b = blockIdx.x/49, l0 = (blockIdx.x%49)*64;
    const float* src = g_xres + (size_t)b*128*LL;
    for (int i=tid;i<8192;i+=256){ int c=i>>6,p=i&63; xt[i] = src[(size_t)c*LL + l0+p]; }
    __syncthreads();
    if (tid < 64){
        float v=0.f;
        #pragma unroll 8
        for(int c=0;c<128;c++){ float a=xt[c*64+tid]; v+=a*a; }
        invp[tid] = rsqrtf(v*(1.f/128.f)+1e-5f);
    }
    __syncthreads();
    int oq = tid>>4, pq = tid&15;
    int o0 = oq*8, p0q = pq*4;
    float acc[8][4];
    #pragma unroll
    for(int i=0;i<8;i++){
        #pragma unroll
        for(int q=0;q<4;q++) acc[i][q]=0.f;
    }
    int jh = tid>>2, ph = (tid&3)*16;
    for (int cc=0; cc<8; cc++){
        // --- w1 chunk ---
        for (int i=tid;i<8192;i+=256){
            int c=i&127, j=i>>7;
            wc[j*128+c] = w1[(size_t)(cc*64+j)*128 + c]*gmlp[c];
        }
        __syncthreads();
        // --- h chunk: thread owns hidden jh, 16 pixels ---
        {
            float a[16];
            #pragma unroll
            for(int q=0;q<16;q++) a[q]=0.f;
            for (int c=0;c<128;c++){
                float w = wc[jh*128+c];
                const float4* xr = (const float4*)(xt + c*64 + ph);
                #pragma unroll
                for(int q4=0;q4<4;q4++){
                    float4 xv = xr[q4];
                    a[q4*4+0] += w*xv.x; a[q4*4+1] += w*xv.y;
                    a[q4*4+2] += w*xv.z; a[q4*4+3] += w*xv.w;
                }
            }
            float bb = b1[cc*64+jh];
            #pragma unroll
            for(int q=0;q<16;q++)
                h[jh*68+ph+q] = gelu_t(a[q]*invp[ph+q] + bb);
        }
        __syncthreads();
        // --- w2 chunk ---
        for (int i=tid;i<8192;i+=256){
            int j=i&63, o=i>>6;
            wc[j*133+o] = w2[(size_t)o*512 + cc*64 + j];
        }
        __syncthreads();
        // --- accumulate out ---
        for (int j=0;j<64;j++){
            float4 hv = *(const float4*)(h + j*68 + p0q);
            const float* wr = wc + j*133 + o0;
            #pragma unroll
            for(int i=0;i<8;i++){
                float w = wr[i];
                acc[i][0] += w*hv.x; acc[i][1] += w*hv.y;
                acc[i][2] += w*hv.z; acc[i][3] += w*hv.w;
            }
        }
        __syncthreads();
    }
    #pragma unroll
    for(int i=0;i<8;i++){
        int o = o0+i;
        float g2 = gamma2[o], bb = b2[o];
        #pragma unroll
        for(int q=0;q<4;q++){
            int p = p0q+q;
            out[((size_t)b*128+o)*LL + l0 + p] = xt[o*64+p] + g2*(acc[i][q] + bb);
        }
    }
}

// ======== launch ========
extern "C" void kernel_launch(void* const* d_in, const int* in_sizes, int n_in,
                              void* d_out, int out_size) {
    const float* x      = (const float*)d_in[0];
    const float* wq     = (const float*)d_in[1];
    const float* wk     = (const float*)d_in[2];
    const float* wv     = (const float*)d_in[3];
    const float* w_proj = (const float*)d_in[4];
    const float* b_proj = (const float*)d_in[5];
    const float* g_q    = (const float*)d_in[6];
    const float* g_k    = (const float*)d_in[7];
    const float* g_v    = (const float*)d_in[8];
    const float* g_vm   = (const float*)d_in[9];
    const float* g_mlp  = (const float*)d_in[10];
    const float* m_in_w = (const float*)d_in[11];
    const float* m_conv_w=(const float*)d_in[12];
    const float* m_conv_b=(const float*)d_in[13];
    const float* m_xproj=(const float*)d_in[14];
    const float* m_dtw  = (const float*)d_in[15];
    const float* m_dtb  = (const float*)d_in[16];
    const float* m_Alog = (const float*)d_in[17];
    const float* m_D    = (const float*)d_in[18];
    const float* m_out_w= (const float*)d_in[19];
    const float* se_w1  = (const float*)d_in[20];
    const float* se_b1  = (const float*)d_in[21];
    const float* se_w2  = (const float*)d_in[22];
    const float* se_b2  = (const float*)d_in[23];
    const float* mlp_w1 = (const float*)d_in[24];
    const float* mlp_b1 = (const float*)d_in[25];
    const float* mlp_w2 = (const float*)d_in[26];
    const float* mlp_b2 = (const float*)d_in[27];
    const float* gamma1 = (const float*)d_in[28];
    const float* gamma2 = (const float*)d_in[29];
    float* out = (float*)d_out;

    static bool attr_done = false;
    if (!attr_done){
        cudaFuncSetAttribute(k_attn,    cudaFuncAttributeMaxDynamicSharedMemorySize, 68000);
        cudaFuncSetAttribute(k_rms_in,  cudaFuncAttributeMaxDynamicSharedMemorySize, 49500);
        cudaFuncSetAttribute(k_xproj,   cudaFuncAttributeMaxDynamicSharedMemorySize, 63200);
        cudaFuncSetAttribute(k_outproj, cudaFuncAttributeMaxDynamicSharedMemorySize, 65600);
        cudaFuncSetAttribute(k_mlp,     cudaFuncAttributeMaxDynamicSharedMemorySize, 84600);
        attr_done = true;
    }

    k_attn<<<1024, 256, 67856>>>(x, wq, wk, wv, w_proj, b_proj, g_q, g_k, g_v);
    k_rms_in<<<16*49, 256, 49408>>>(x, m_in_w, g_vm);
    k_dwconv<<<16*128, 256>>>(m_conv_w, m_conv_b);
    k_transpose<<<16*128, 256>>>();
    k_xproj<<<16*196, 256, 63120>>>(m_xproj, m_dtw, m_dtb);
    k_scan<<<128, 128>>>(m_Alog, m_D);
    k_merge<<<16*128, 256>>>();
    k_outproj<<<16*49, 256, 65536>>>(m_out_w);
    k_pool<<<2048, 256>>>();
    k_se<<<16, 128>>>(se_w1, se_b1, se_w2, se_b2);
    {
        size_t N = (size_t)NB*128*LL;
        k_resid<<<(unsigned)((N + 255)/256), 256>>>(x, gamma1);
    }
    k_mlp<<<16*49, 256, 84480>>>(g_mlp, mlp_w1, mlp_b1, mlp_w2, mlp_b2, gamma2, out);
}

// round 12
// speedup vs baseline: 1.9254x; 1.9254x over previous
#include <cuda_runtime.h>
#include <math.h>

#define LL 3136
#define NB 16
#define CH 16
#define CL 196

// ---------------- scratch ----------------
__device__ float g_y[(size_t)NB*128*LL];
__device__ float g_xin[(size_t)NB*128*LL];
__device__ float g_xconv[(size_t)NB*128*LL];
__device__ float g_xconvT[(size_t)NB*128*LL];
__device__ float g_yg[(size_t)NB*128*LL];
__device__ float g_xres[(size_t)NB*128*LL];
__device__ float g_delta[(size_t)NB*4*128*LL];
__device__ float g_ys[(size_t)NB*4*128*LL];
__device__ float g_Bc[(size_t)NB*4*LL*16];
__device__ float g_Cc[(size_t)NB*4*LL*16];
__device__ float g_hend[(size_t)8192*256];
__device__ float g_sdl[(size_t)8192*CH];
__device__ float g_p[2048];
__device__ float g_s[2048];

__device__ __forceinline__ float gelu_t(float x){
    float a = 1.5957691216057308f*(x + 0.044715f*x*x*x);
    return x / (1.f + __expf(-a));
}

// ======== K1: window attention (unchanged this round) ========
__global__ void k_attn(const float* __restrict__ x,
    const float* __restrict__ wq, const float* __restrict__ wk, const float* __restrict__ wv,
    const float* __restrict__ wp, const float* __restrict__ bp,
    const float* __restrict__ gq, const float* __restrict__ gk, const float* __restrict__ gv)
{
    extern __shared__ float sm[];
    float* xs  = sm;
    float* qs  = xs + 3185;
    float* ks  = qs + 3185;
    float* vs  = ks + 3185;
    float* wb  = vs + 3185;
    float* inv = wb + 4160;
    int tid = threadIdx.x;
    int wi = blockIdx.x;
    int b = wi >> 6, wy = (wi >> 3) & 7, wx = wi & 7;
    const float* xb = x + (size_t)b*128*LL;
    for (int i = tid; i < 49*64; i += 256){
        int c = i / 49, t = i % 49;
        xs[t*65+c] = xb[(size_t)c*LL + (wy*7 + t/7)*56 + wx*7 + t%7];
    }
    __syncthreads();
    if (tid < 49){
        float v = 0.f;
        for (int c=0;c<64;c++){ float a = xs[tid*65+c]; v += a*a; }
        inv[tid] = rsqrtf(v*(1.f/64.f) + 1e-5f);
    }
    __syncthreads();
    const float* Wm[3] = {wq,wk,wv};
    const float* Gm[3] = {gq,gk,gv};
    float* Dst[3] = {qs,ks,vs};
    for (int m=0;m<3;m++){
        for (int i = tid; i < 64*64; i += 256){
            int o = i >> 6, c = i & 63;
            wb[o*65+c] = Wm[m][o*64+c]*Gm[m][c];
        }
        __syncthreads();
        for (int i = tid; i < 49*64; i += 256){
            int t = i >> 6, o = i & 63;
            float acc = 0.f;
            #pragma unroll 8
            for (int c=0;c<64;c++) acc += xs[t*65+c]*wb[o*65+c];
            Dst[m][t*65+o] = acc*inv[t];
        }
        __syncthreads();
    }
    float* ss = wb;
    float* os = xs;
    const float scale = 0.3535533905932738f;
    for (int hh=0; hh<8; hh++){
        for (int i=tid; i<49*49; i+=256){
            int t = i/49, u = i%49;
            float acc=0.f;
            #pragma unroll
            for(int j=0;j<8;j++) acc += qs[t*65+hh*8+j]*ks[u*65+hh*8+j];
            ss[t*49+u] = acc*scale;
        }
        __syncthreads();
        if (tid < 49){
            float mx = -1e30f;
            for(int u=0;u<49;u++) mx = fmaxf(mx, ss[tid*49+u]);
            float sum=0.f;
            for(int u=0;u<49;u++){ float e=__expf(ss[tid*49+u]-mx); ss[tid*49+u]=e; sum+=e; }
            float r = 1.f/sum;
            for(int u=0;u<49;u++) ss[tid*49+u]*=r;
        }
        __syncthreads();
        for (int i=tid; i<49*8; i+=256){
            int t = i>>3, j = i&7;
            float acc=0.f;
            for(int u=0;u<49;u++) acc += ss[t*49+u]*vs[u*65+hh*8+j];
            os[t*65+hh*8+j] = acc;
        }
        __syncthreads();
    }
    for (int i=tid;i<64*64;i+=256){ int o=i>>6,c=i&63; wb[o*65+c]=wp[o*64+c]; }
    __syncthreads();
    for (int i=tid;i<49*64;i+=256){
        int o = i/49, t = i%49;
        float acc = bp[o];
        #pragma unroll 8
        for(int c=0;c<64;c++) acc += os[t*65+c]*wb[o*65+c];
        g_y[((size_t)b*128+o)*LL + (wy*7 + t/7)*56 + wx*7 + t%7] = acc;
    }
}

// ======== K2a: rms2d + in-proj 64->128 (4x4 register tiles) ========
__global__ void k_rms_in(const float* __restrict__ x, const float* __restrict__ min_w,
                         const float* __restrict__ gvm)
{
    extern __shared__ float sm[];
    float* xt  = sm;            // [64 c][64 p]
    float* ws  = xt + 4096;     // [64 c][132] transposed weight
    float* inv = ws + 8448;
    int tid = threadIdx.x;
    int b = blockIdx.x / 49, l0 = (blockIdx.x % 49)*64;
    const float* x2 = x + ((size_t)b*128 + 64)*LL;
    for (int i=tid;i<4096;i+=256){ int c=i>>6,p=i&63; xt[i] = x2[(size_t)c*LL + l0+p]; }
    for (int i=tid;i<8192;i+=256){ int d=i>>6,c=i&63; ws[c*132+d] = min_w[i]*__ldg(gvm+c); }
    __syncthreads();
    if (tid<64){ float v=0.f;
        #pragma unroll 8
        for(int c=0;c<64;c++){float a=xt[c*64+tid]; v+=a*a;}
        inv[tid]=rsqrtf(v*(1.f/64.f)+1e-5f); }
    __syncthreads();
    int pg = tid & 15, p0 = pg*4;
    int d0a = (tid>>4)*4, d0b = d0a + 64;
    float A[2][4][4];
    #pragma unroll
    for(int t=0;t<2;t++)for(int i=0;i<4;i++)for(int q=0;q<4;q++) A[t][i][q]=0.f;
    for (int c=0;c<64;c++){
        float4 xv = *(const float4*)(xt + c*64 + p0);
        float4 wa = *(const float4*)(ws + c*132 + d0a);
        float4 wb2= *(const float4*)(ws + c*132 + d0b);
        float wv[2][4] = {{wa.x,wa.y,wa.z,wa.w},{wb2.x,wb2.y,wb2.z,wb2.w}};
        #pragma unroll
        for(int t=0;t<2;t++){
            #pragma unroll
            for(int i=0;i<4;i++){
                A[t][i][0]+=wv[t][i]*xv.x; A[t][i][1]+=wv[t][i]*xv.y;
                A[t][i][2]+=wv[t][i]*xv.z; A[t][i][3]+=wv[t][i]*xv.w;
            }
        }
    }
    #pragma unroll
    for(int t=0;t<2;t++){
        int d0 = t? d0b : d0a;
        #pragma unroll
        for(int i=0;i<4;i++)
            #pragma unroll
            for(int q=0;q<4;q++)
                g_xin[((size_t)b*128+d0+i)*LL + l0+p0+q] = A[t][i][q]*inv[p0+q];
    }
}

// ======== K2b: depthwise 3x3 + bias + silu ========
__global__ void k_dwconv(const float* __restrict__ cw, const float* __restrict__ cb)
{
    __shared__ float t[58*58];
    int bd = blockIdx.x, d = bd & 127, tid = threadIdx.x;
    const float* src = g_xin + (size_t)bd*LL;
    for (int i=tid;i<58*58;i+=256){
        int hh = i/58 - 1, ww = i%58 - 1;
        t[i] = (hh>=0 && hh<56 && ww>=0 && ww<56) ? src[hh*56+ww] : 0.f;
    }
    float w9[9];
    #pragma unroll
    for(int j=0;j<9;j++) w9[j] = cw[d*9+j];
    float bias = cb[d];
    __syncthreads();
    float* dst = g_xconv + (size_t)bd*LL;
    for (int i=tid;i<LL;i+=256){
        const float* tp = t + (i/56)*58 + i%56;
        float a = bias;
        #pragma unroll
        for(int dy=0;dy<3;dy++)
            #pragma unroll
            for(int dx=0;dx<3;dx++) a += w9[dy*3+dx]*tp[dy*58+dx];
        dst[i] = a / (1.f + __expf(-a));
    }
}

// ======== K2c: per-plane transpose ========
__global__ void k_transpose(){
    __shared__ float t[56*57];
    int bd = blockIdx.x, tid = threadIdx.x;
    const float* src = g_xconv + (size_t)bd*LL;
    float* dst = g_xconvT + (size_t)bd*LL;
    for(int i=tid;i<LL;i+=256) t[(i/56)*57 + i%56] = src[i];
    __syncthreads();
    for(int j=tid;j<LL;j+=256) dst[j] = t[(j%56)*57 + j/56];
}

// ======== K3: xproj + dt + softplus -> delta/B/C (4x4 tiled GEMM) ========
__global__ void k_xproj(const float* __restrict__ xproj, const float* __restrict__ dtw,
                        const float* __restrict__ dtb)
{
    extern __shared__ float sm[];
    float* xt    = sm;              // [128 d][64 p]
    float* wp_   = xt + 8192;       // [128 d][36 c]
    float* xd    = wp_ + 4608;      // [36][65]
    float* dtw_s = xd + 2340;
    float* dtb_s = dtw_s + 512;
    int tid = threadIdx.x, blk = blockIdx.x;
    int b = blk / 196, r = blk % 196, k = r / 49, l0 = (r%49)*64;
    const float* src = ((k&1)? g_xconvT : g_xconv) + (size_t)b*128*LL;
    bool rev = k >= 2;
    for (int i=tid;i<8192;i+=256){
        int d=i>>6,p=i&63;
        int pos = rev ? (LL-1-(l0+p)) : (l0+p);
        xt[i] = src[(size_t)d*LL + pos];
    }
    for (int i=tid;i<4608;i+=256) wp_[i] = xproj[(size_t)k*4608 + i];
    for (int i=tid;i<512;i+=256) dtw_s[i] = dtw[k*512+i];
    if (tid<128) dtb_s[tid] = dtb[k*128+tid];
    __syncthreads();
    if (tid < 144){
        int c0 = (tid>>4)*4, p0 = (tid&15)*4;
        float A[4][4];
        #pragma unroll
        for(int i=0;i<4;i++)for(int q=0;q<4;q++) A[i][q]=0.f;
        for (int d=0;d<128;d++){
            float4 w4 = *(const float4*)(wp_ + d*36 + c0);
            float4 x4 = *(const float4*)(xt + d*64 + p0);
            float wv[4] = {w4.x,w4.y,w4.z,w4.w};
            #pragma unroll
            for(int i=0;i<4;i++){
                A[i][0]+=wv[i]*x4.x; A[i][1]+=wv[i]*x4.y;
                A[i][2]+=wv[i]*x4.z; A[i][3]+=wv[i]*x4.w;
            }
        }
        #pragma unroll
        for(int i=0;i<4;i++)
            #pragma unroll
            for(int q=0;q<4;q++) xd[(c0+i)*65 + p0+q] = A[i][q];
    }
    __syncthreads();
    size_t dbase = ((size_t)(b*4 + k)*128)*LL;
    for (int i=tid;i<8192;i+=256){
        int d=i>>6,p=i&63;
        float a = dtb_s[d];
        #pragma unroll
        for(int rr=0;rr<4;rr++) a += xd[rr*65+p]*dtw_s[d*4+rr];
        float sp = (a > 20.f) ? a : log1pf(__expf(a));
        g_delta[dbase + (size_t)d*LL + l0 + p] = sp;
    }
    size_t bcbase = ((size_t)(b*4+k)*LL + l0)*16;
    for (int i=tid;i<1024;i+=256){
        int p = i>>4, n = i&15;
        g_Bc[bcbase + (size_t)p*16 + n] = xd[(4+n)*65+p];
        g_Cc[bcbase + (size_t)p*16 + n] = xd[(20+n)*65+p];
    }
}

// ======== K4: chunked selective scan ========
// pass 1: per chunk, h from 0 -> store h_end(0-init) and sum(delta)
__global__ void __launch_bounds__(128) k_scan1(const float* __restrict__ Alog)
{
    int blk = blockIdx.x;                 // 2048
    int ch = blk & 15, sb = blk >> 4;
    int b = sb >> 3, k = (sb>>1)&3, half = sb&1;
    int wid = threadIdx.x >> 5, lane = threadIdx.x & 31;
    int s = lane >> 1, sub = lane & 1;
    int d = half*64 + wid*16 + s;
    size_t seq = (size_t)(b*4+k)*128 + d;
    const float* dptr = g_delta + seq*LL;
    const float* uptr = ((k&1)? g_xconvT : g_xconv) + ((size_t)b*128 + d)*LL;
    bool rev = k>=2;
    float A[8];
    #pragma unroll
    for(int j=0;j<8;j++) A[j] = -__expf(__ldg(Alog + ((size_t)k*128+d)*16 + sub*8 + j));
    const float4* B4 = (const float4*)(g_Bc + (size_t)(b*4+k)*LL*16) + sub*2;
    float h0=0,h1=0,h2=0,h3=0,h4=0,h5=0,h6=0,h7=0, sdl=0.f;
    int t0 = ch*CL;
    for (int tt=0;tt<CL;tt++){
        int t = t0+tt;
        int pos = rev ? (LL-1-t) : t;
        float dl = __ldg(dptr + t);
        float u  = __ldg(uptr + pos);
        float4 ba = __ldg(B4 + (size_t)t*4);
        float4 bb = __ldg(B4 + (size_t)t*4 + 1);
        float du = dl*u;
        h0 = __expf(dl*A[0])*h0 + du*ba.x;
        h1 = __expf(dl*A[1])*h1 + du*ba.y;
        h2 = __expf(dl*A[2])*h2 + du*ba.z;
        h3 = __expf(dl*A[3])*h3 + du*ba.w;
        h4 = __expf(dl*A[4])*h4 + du*bb.x;
        h5 = __expf(dl*A[5])*h5 + du*bb.y;
        h6 = __expf(dl*A[6])*h6 + du*bb.z;
        h7 = __expf(dl*A[7])*h7 + du*bb.w;
        sdl += dl;
    }
    size_t base = seq*256 + ch*16 + sub*8;
    g_hend[base+0]=h0; g_hend[base+1]=h1; g_hend[base+2]=h2; g_hend[base+3]=h3;
    g_hend[base+4]=h4; g_hend[base+5]=h5; g_hend[base+6]=h6; g_hend[base+7]=h7;
    if (sub==0) g_sdl[seq*16+ch] = sdl;
}
// pass 1.5: chain chunk states (in-place: g_hend becomes h_in per chunk)
__global__ void k_fix(const float* __restrict__ Alog)
{
    int idx = blockIdx.x*256 + threadIdx.x;   // 131072
    int seq = idx >> 4, st = idx & 15;
    int k = (seq>>7)&3, d = seq&127;
    float A = -__expf(__ldg(Alog + ((size_t)k*128+d)*16 + st));
    float h = 0.f;
    #pragma unroll
    for (int c=0;c<CH;c++){
        size_t o = (size_t)seq*256 + c*16 + st;
        float he = g_hend[o];
        g_hend[o] = h;
        h = __expf(A*g_sdl[seq*16+c])*h + he;
    }
}
// pass 2: rescan chunk with true h_in, emit y
__global__ void __launch_bounds__(128) k_scan2(const float* __restrict__ Alog,
                                               const float* __restrict__ Dp)
{
    int blk = blockIdx.x;
    int ch = blk & 15, sb = blk >> 4;
    int b = sb >> 3, k = (sb>>1)&3, half = sb&1;
    int wid = threadIdx.x >> 5, lane = threadIdx.x & 31;
    int s = lane >> 1, sub = lane & 1;
    int d = half*64 + wid*16 + s;
    size_t seq = (size_t)(b*4+k)*128 + d;
    const float* dptr = g_delta + seq*LL;
    const float* uptr = ((k&1)? g_xconvT : g_xconv) + ((size_t)b*128 + d)*LL;
    float* yptr = g_ys + seq*LL;
    bool rev = k>=2;
    float A[8];
    #pragma unroll
    for(int j=0;j<8;j++) A[j] = -__expf(__ldg(Alog + ((size_t)k*128+d)*16 + sub*8 + j));
    float Dv = __ldg(Dp + k*128 + d);
    const float4* B4 = (const float4*)(g_Bc + (size_t)(b*4+k)*LL*16) + sub*2;
    const float4* C4 = (const float4*)(g_Cc + (size_t)(b*4+k)*LL*16) + sub*2;
    size_t base = seq*256 + ch*16 + sub*8;
    float h0=g_hend[base+0],h1=g_hend[base+1],h2=g_hend[base+2],h3=g_hend[base+3];
    float h4=g_hend[base+4],h5=g_hend[base+5],h6=g_hend[base+6],h7=g_hend[base+7];
    int t0 = ch*CL;
    for (int tt=0;tt<CL;tt++){
        int t = t0+tt;
        int pos = rev ? (LL-1-t) : t;
        float dl = __ldg(dptr + t);
        float u  = __ldg(uptr + pos);
        float4 ba = __ldg(B4 + (size_t)t*4);
        float4 bb = __ldg(B4 + (size_t)t*4 + 1);
        float4 ca = __ldg(C4 + (size_t)t*4);
        float4 cb = __ldg(C4 + (size_t)t*4 + 1);
        float du = dl*u, y;
        h0 = __expf(dl*A[0])*h0 + du*ba.x; y  = h0*ca.x;
        h1 = __expf(dl*A[1])*h1 + du*ba.y; y += h1*ca.y;
        h2 = __expf(dl*A[2])*h2 + du*ba.z; y += h2*ca.z;
        h3 = __expf(dl*A[3])*h3 + du*ba.w; y += h3*ca.w;
        h4 = __expf(dl*A[4])*h4 + du*bb.x; y += h4*cb.x;
        h5 = __expf(dl*A[5])*h5 + du*bb.y; y += h5*cb.y;
        h6 = __expf(dl*A[6])*h6 + du*bb.z; y += h6*cb.z;
        h7 = __expf(dl*A[7])*h7 + du*bb.w; y += h7*cb.w;
        y += __shfl_xor_sync(0xffffffffu, y, 1);
        if (sub == 0) yptr[pos] = y + Dv*u;
    }
}

// ======== K4b: cross-merge + gelu ========
__global__ void k_merge(){
    __shared__ float t[56*57];
    int bd = blockIdx.x, b = bd >> 7, d = bd & 127, tid = threadIdx.x;
    size_t base = ((size_t)b*4)*128*LL + (size_t)d*LL;
    const float* y0 = g_ys + base;
    const float* y1 = g_ys + base + (size_t)128*LL;
    const float* y2 = g_ys + base + (size_t)2*128*LL;
    const float* y3 = g_ys + base + (size_t)3*128*LL;
    for (int j=tid;j<LL;j+=256) t[(j/56)*57 + j%56] = y1[j] + y3[j];
    __syncthreads();
    float* dst = g_yg + ((size_t)b*128 + d)*LL;
    for (int i=tid;i<LL;i+=256){
        float v = y0[i] + y2[i] + t[(i%56)*57 + i/56];
        dst[i] = gelu_t(v);
    }
}

// ======== K5: out-proj 128->64 (4x4 tiles) ========
__global__ void k_outproj(const float* __restrict__ ow){
    extern __shared__ float sm[];
    float* ws = sm;            // [128 d][68] transposed
    float* yt = ws + 8704;     // [128 d][64 p]
    int tid=threadIdx.x;
    int b = blockIdx.x/49, l0=(blockIdx.x%49)*64;
    for (int i=tid;i<8192;i+=256){ int o=i>>7, d=i&127; ws[d*68+o]=ow[i]; }
    const float* src = g_yg + (size_t)b*128*LL;
    for (int i=tid;i<8192;i+=256){ int d=i>>6,p=i&63; yt[i]=src[(size_t)d*LL+l0+p]; }
    __syncthreads();
    int o0=(tid>>4)*4, p0=(tid&15)*4;
    float A[4][4];
    #pragma unroll
    for(int i=0;i<4;i++)for(int q=0;q<4;q++) A[i][q]=0.f;
    for (int d=0;d<128;d++){
        float4 w4 = *(const float4*)(ws + d*68 + o0);
        float4 y4 = *(const float4*)(yt + d*64 + p0);
        float wv[4] = {w4.x,w4.y,w4.z,w4.w};
        #pragma unroll
        for(int i=0;i<4;i++){
            A[i][0]+=wv[i]*y4.x; A[i][1]+=wv[i]*y4.y;
            A[i][2]+=wv[i]*y4.z; A[i][3]+=wv[i]*y4.w;
        }
    }
    #pragma unroll
    for(int i=0;i<4;i++)
        #pragma unroll
        for(int q=0;q<4;q++)
            g_y[((size_t)b*128 + 64 + o0+i)*LL + l0+p0+q] = A[i][q];
}

// ======== K6: SE pool / gate / residual ========
__global__ void k_pool(){
    __shared__ float red[256];
    int bc = blockIdx.x, tid = threadIdx.x;
    const float* src = g_y + (size_t)bc*LL;
    float s=0.f;
    for(int i=tid;i<LL;i+=256) s += src[i];
    red[tid]=s; __syncthreads();
    for(int o=128;o>0;o>>=1){ if(tid<o) red[tid]+=red[tid+o]; __syncthreads(); }
    if(tid==0) g_p[bc] = red[0]*(1.f/LL);
}
__global__ void k_se(const float* __restrict__ w1, const float* __restrict__ b1,
                     const float* __restrict__ w2, const float* __restrict__ b2){
    __shared__ float p[128], hid[32];
    int b = blockIdx.x, tid = threadIdx.x;
    if (tid<128) p[tid] = g_p[b*128+tid];
    __syncthreads();
    if (tid<32){
        float a = b1[tid];
        #pragma unroll 8
        for(int c=0;c<128;c++) a += w1[tid*128+c]*p[c];
        hid[tid] = fmaxf(a, 0.f);
    }
    __syncthreads();
    if (tid<128){
        float a = b2[tid];
        #pragma unroll
        for(int j=0;j<32;j++) a += w2[tid*32+j]*hid[j];
        g_s[b*128+tid] = 1.f/(1.f+__expf(-a));
    }
}
__global__ void k_resid(const float* __restrict__ x, const float* __restrict__ gamma1){
    size_t i = (size_t)blockIdx.x*256 + threadIdx.x;
    if (i >= (size_t)NB*128*LL) return;
    int bc = (int)(i / LL);
    int c = bc & 127;
    g_xres[i] = x[i] + gamma1[c]*g_s[bc]*g_y[i];
}

// ======== K7: fused RMS + MLP(128->512->128) + residual ========
__global__ void __launch_bounds__(256) k_mlp(
    const float* __restrict__ gmlp,
    const float* __restrict__ w1, const float* __restrict__ b1,
    const float* __restrict__ w2, const float* __restrict__ b2,
    const float* __restrict__ gamma2, float* __restrict__ out)
{
    extern __shared__ float sm[];
    float* xt   = sm;            // [128 c][64 p]
    float* h    = xt + 8192;     // [64 j][68 p]
    float* wc   = h + 4352;      // pass1: [128 c][68 j]; pass2: [64 j][132 o]
    float* invp = wc + 8704;     // 64
    int tid = threadIdx.x;
    int b = blockIdx.x/49, l0 = (blockIdx.x%49)*64;
    const float* src = g_xres + (size_t)b*128*LL;
    for (int i=tid;i<8192;i+=256){ int c=i>>6,p=i&63; xt[i] = src[(size_t)c*LL + l0+p]; }
    __syncthreads();
    if (tid < 64){
        float v=0.f;
        #pragma unroll 8
        for(int c=0;c<128;c++){ float a=xt[c*64+tid]; v+=a*a; }
        invp[tid] = rsqrtf(v*(1.f/128.f)+1e-5f);
    }
    __syncthreads();
    int oq = tid>>4, pq = tid&15;
    int o0 = oq*8, p0q = pq*4;
    float acc[8][4];
    #pragma unroll
    for(int i=0;i<8;i++)for(int q=0;q<4;q++) acc[i][q]=0.f;
    int j0 = (tid&15)*4, p1 = (tid>>4)*4;
    for (int cc=0; cc<8; cc++){
        // --- w1 chunk, transposed [c][68] with gmlp folded in ---
        for (int i=tid;i<2048;i+=256){
            int j = i>>5, c0 = (i&31)*4;
            float4 wv = *(const float4*)(w1 + (size_t)(cc*64+j)*128 + c0);
            wc[(c0+0)*68+j] = wv.x*__ldg(gmlp+c0+0);
            wc[(c0+1)*68+j] = wv.y*__ldg(gmlp+c0+1);
            wc[(c0+2)*68+j] = wv.z*__ldg(gmlp+c0+2);
            wc[(c0+3)*68+j] = wv.w*__ldg(gmlp+c0+3);
        }
        __syncthreads();
        // --- h chunk: 4 hiddens x 4 pixels per thread ---
        {
            float A[4][4];
            #pragma unroll
            for(int i=0;i<4;i++)for(int q=0;q<4;q++) A[i][q]=0.f;
            for (int c=0;c<128;c++){
                float4 w4 = *(const float4*)(wc + c*68 + j0);
                float4 x4 = *(const float4*)(xt + c*64 + p1);
                float wv[4] = {w4.x,w4.y,w4.z,w4.w};
                #pragma unroll
                for(int i=0;i<4;i++){
                    A[i][0]+=wv[i]*x4.x; A[i][1]+=wv[i]*x4.y;
                    A[i][2]+=wv[i]*x4.z; A[i][3]+=wv[i]*x4.w;
                }
            }
            #pragma unroll
            for(int i=0;i<4;i++){
                float bb = b1[cc*64+j0+i];
                #pragma unroll
                for(int q=0;q<4;q++)
                    h[(j0+i)*68 + p1+q] = gelu_t(A[i][q]*invp[p1+q] + bb);
            }
        }
        __syncthreads();
        // --- w2 chunk [j][132] ---
        for (int i=tid;i<8192;i+=256){
            int j=i&63, o=i>>6;
            wc[j*132+o] = w2[(size_t)o*512 + cc*64 + j];
        }
        __syncthreads();
        // --- accumulate out: 8 o x 4 p per thread ---
        for (int j=0;j<64;j++){
            float4 hv = *(const float4*)(h + j*68 + p0q);
            const float* wr = wc + j*132 + o0;
            #pragma unroll
            for(int i=0;i<8;i++){
                float w = wr[i];
                acc[i][0] += w*hv.x; acc[i][1] += w*hv.y;
                acc[i][2] += w*hv.z; acc[i][3] += w*hv.w;
            }
        }
        __syncthreads();
    }
    #pragma unroll
    for(int i=0;i<8;i++){
        int o = o0+i;
        float g2 = gamma2[o], bb = b2[o];
        #pragma unroll
        for(int q=0;q<4;q++){
            int p = p0q+q;
            out[((size_t)b*128+o)*LL + l0 + p] = xt[o*64+p] + g2*(acc[i][q] + bb);
        }
    }
}

// ======== launch ========
extern "C" void kernel_launch(void* const* d_in, const int* in_sizes, int n_in,
                              void* d_out, int out_size) {
    const float* x      = (const float*)d_in[0];
    const float* wq     = (const float*)d_in[1];
    const float* wk     = (const float*)d_in[2];
    const float* wv     = (const float*)d_in[3];
    const float* w_proj = (const float*)d_in[4];
    const float* b_proj = (const float*)d_in[5];
    const float* g_q    = (const float*)d_in[6];
    const float* g_k    = (const float*)d_in[7];
    const float* g_v    = (const float*)d_in[8];
    const float* g_vm   = (const float*)d_in[9];
    const float* g_mlp  = (const float*)d_in[10];
    const float* m_in_w = (const float*)d_in[11];
    const float* m_conv_w=(const float*)d_in[12];
    const float* m_conv_b=(const float*)d_in[13];
    const float* m_xproj=(const float*)d_in[14];
    const float* m_dtw  = (const float*)d_in[15];
    const float* m_dtb  = (const float*)d_in[16];
    const float* m_Alog = (const float*)d_in[17];
    const float* m_D    = (const float*)d_in[18];
    const float* m_out_w= (const float*)d_in[19];
    const float* se_w1  = (const float*)d_in[20];
    const float* se_b1  = (const float*)d_in[21];
    const float* se_w2  = (const float*)d_in[22];
    const float* se_b2  = (const float*)d_in[23];
    const float* mlp_w1 = (const float*)d_in[24];
    const float* mlp_b1 = (const float*)d_in[25];
    const float* mlp_w2 = (const float*)d_in[26];
    const float* mlp_b2 = (const float*)d_in[27];
    const float* gamma1 = (const float*)d_in[28];
    const float* gamma2 = (const float*)d_in[29];
    float* out = (float*)d_out;

    static bool attr_done = false;
    if (!attr_done){
        cudaFuncSetAttribute(k_attn,    cudaFuncAttributeMaxDynamicSharedMemorySize, 68000);
        cudaFuncSetAttribute(k_rms_in,  cudaFuncAttributeMaxDynamicSharedMemorySize, 50432);
        cudaFuncSetAttribute(k_xproj,   cudaFuncAttributeMaxDynamicSharedMemorySize, 63200);
        cudaFuncSetAttribute(k_outproj, cudaFuncAttributeMaxDynamicSharedMemorySize, 67584);
        cudaFuncSetAttribute(k_mlp,     cudaFuncAttributeMaxDynamicSharedMemorySize, 85504);
        attr_done = true;
    }

    k_attn<<<1024, 256, 67856>>>(x, wq, wk, wv, w_proj, b_proj, g_q, g_k, g_v);
    k_rms_in<<<16*49, 256, 50432>>>(x, m_in_w, g_vm);
    k_dwconv<<<16*128, 256>>>(m_conv_w, m_conv_b);
    k_transpose<<<16*128, 256>>>();
    k_xproj<<<16*196, 256, 63120>>>(m_xproj, m_dtw, m_dtb);
    k_scan1<<<2048, 128>>>(m_Alog);
    k_fix<<<512, 256>>>(m_Alog);
    k_scan2<<<2048, 128>>>(m_Alog, m_D);
    k_merge<<<16*128, 256>>>();
    k_outproj<<<16*49, 256, 67584>>>(m_out_w);
    k_pool<<<2048, 256>>>();
    k_se<<<16, 128>>>(se_w1, se_b1, se_w2, se_b2);
    {
        size_t N = (size_t)NB*128*LL;
        k_resid<<<(unsigned)((N + 255)/256), 256>>>(x, gamma1);
    }
    k_mlp<<<16*49, 256, 85248>>>(g_mlp, mlp_w1, mlp_b1, mlp_w2, mlp_b2, gamma2, out);
}

// round 14
// speedup vs baseline: 2.1283x; 1.1054x over previous
#include <cuda_runtime.h>
#include <math.h>

#define LL 3136
#define NB 16
#define CH 16
#define CL 196

typedef unsigned long long ull;

// ---------------- scratch ----------------
__device__ float g_y[(size_t)NB*128*LL];
__device__ float g_xin[(size_t)NB*128*LL];
__device__ float g_xconv[(size_t)NB*128*LL];
__device__ float g_xconvT[(size_t)NB*128*LL];
__device__ float g_yg[(size_t)NB*128*LL];
__device__ float g_xres[(size_t)NB*128*LL];
__device__ float2 g_dd[(size_t)NB*4*LL*128];   // (delta, delta*u) in scan order [t][d]
__device__ float g_ys[(size_t)NB*4*128*LL];
__device__ float g_Bc[(size_t)NB*4*LL*16];
__device__ float g_Cc[(size_t)NB*4*LL*16];
__device__ float g_hend[(size_t)8192*256];
__device__ float g_sdl[(size_t)8192*CH];
__device__ float g_p[2048];
__device__ float g_s[2048];

__device__ __forceinline__ float gelu_t(float x){
    float a = 1.5957691216057308f*(x + 0.044715f*x*x*x);
    return x / (1.f + __expf(-a));
}
__device__ __forceinline__ ull pk2(float a, float b){
    ull r; asm("mov.b64 %0, {%1,%2};" : "=l"(r) : "f"(a), "f"(b)); return r;
}
__device__ __forceinline__ ull dup2(float a){ return pk2(a,a); }
__device__ __forceinline__ void fma2(ull& d, ull a, ull b){
    asm("fma.rn.f32x2 %0, %1, %2, %0;" : "+l"(d) : "l"(a), "l"(b));
}
__device__ __forceinline__ float2 unpk(ull v){
    float2 r; asm("mov.b64 {%0,%1}, %2;" : "=f"(r.x), "=f"(r.y) : "l"(v)); return r;
}

// ======== K1: window attention (tiled fma2 GEMMs + warp softmax) ========
__global__ void __launch_bounds__(256) k_attn(const float* __restrict__ x,
    const float* __restrict__ wq, const float* __restrict__ wk, const float* __restrict__ wv,
    const float* __restrict__ wp, const float* __restrict__ bp,
    const float* __restrict__ gq, const float* __restrict__ gk, const float* __restrict__ gv)
{
    extern __shared__ float sm[];
    float* xsT = sm;           // [64 c][64 t] x*inv; reused as osT[c][t] after QKV
    float* wT  = xsT + 4096;   // [64 c][68 o]
    float* qs  = wT + 4352;    // [64 t][68]; reused for proj result
    float* ks  = qs + 4352;
    float* vs  = ks + 4352;
    float* ss  = vs + 4352;    // [49][50]
    float* inv = ss + 2450;    // 64
    int tid = threadIdx.x;
    int wi = blockIdx.x;
    int b = wi >> 6, wy = (wi >> 3) & 7, wx = wi & 7;
    const float* xb = x + (size_t)b*128*LL;
    for (int i=tid;i<4096;i+=256){
        int c=i>>6, t=i&63;
        xsT[c*64+t] = (t<49) ? xb[(size_t)c*LL + (wy*7+t/7)*56 + wx*7 + t%7] : 0.f;
    }
    __syncthreads();
    if (tid<64){
        float v=0.f;
        #pragma unroll 8
        for(int c=0;c<64;c++){ float a=xsT[c*64+tid]; v+=a*a; }
        inv[tid] = (tid<49)? rsqrtf(v*(1.f/64.f)+1e-5f) : 0.f;
    }
    __syncthreads();
    for (int i=tid;i<4096;i+=256) xsT[i] *= inv[i&63];
    __syncthreads();
    const float* Wm[3]={wq,wk,wv};
    const float* Gm[3]={gq,gk,gv};
    float* Dst[3]={qs,ks,vs};
    int o0=(tid>>4)*4, t0=(tid&15)*4;
    #pragma unroll
    for (int m=0;m<3;m++){
        for (int i=tid;i<4096;i+=256){ int o=i>>6,c=i&63; wT[c*68+o]=Wm[m][o*64+c]*Gm[m][c]; }
        __syncthreads();
        ull a2[4][2];
        #pragma unroll
        for(int i=0;i<4;i++){ a2[i][0]=0ull; a2[i][1]=0ull; }
        for (int c=0;c<64;c++){
            ulonglong2 x2 = *(const ulonglong2*)(xsT + c*64 + t0);
            float4 w4 = *(const float4*)(wT + c*68 + o0);
            ull w0=dup2(w4.x),w1=dup2(w4.y),w2=dup2(w4.z),w3=dup2(w4.w);
            fma2(a2[0][0],w0,x2.x); fma2(a2[0][1],w0,x2.y);
            fma2(a2[1][0],w1,x2.x); fma2(a2[1][1],w1,x2.y);
            fma2(a2[2][0],w2,x2.x); fma2(a2[2][1],w2,x2.y);
            fma2(a2[3][0],w3,x2.x); fma2(a2[3][1],w3,x2.y);
        }
        float* D = Dst[m];
        #pragma unroll
        for(int i=0;i<4;i++){
            float2 v01=unpk(a2[i][0]), v23=unpk(a2[i][1]);
            D[(t0+0)*68+o0+i]=v01.x;
            D[(t0+1)*68+o0+i]=v01.y;
            D[(t0+2)*68+o0+i]=v23.x;
            D[(t0+3)*68+o0+i]=v23.y;
        }
        __syncthreads();
    }
    const float scale = 0.3535533905932738f;
    int wid = tid>>5, lane = tid&31;
    for (int hh=0;hh<8;hh++){
        for (int i=tid;i<2401;i+=256){
            int t=i/49, u=i%49;
            float acc=0.f;
            #pragma unroll
            for(int j=0;j<8;j++) acc += qs[t*68+hh*8+j]*ks[u*68+hh*8+j];
            ss[t*50+u]=acc*scale;
        }
        __syncthreads();
        for (int t=wid; t<49; t+=8){
            float v0 = ss[t*50+lane];
            float v1 = (lane<17)? ss[t*50+lane+32] : -1e30f;
            float m = fmaxf(v0,v1);
            #pragma unroll
            for(int o=16;o>0;o>>=1) m = fmaxf(m, __shfl_xor_sync(0xffffffffu,m,o));
            float e0 = __expf(v0-m), e1 = (lane<17)? __expf(v1-m) : 0.f;
            float s_ = e0+e1;
            #pragma unroll
            for(int o=16;o>0;o>>=1) s_ += __shfl_xor_sync(0xffffffffu,s_,o);
            float r = 1.f/s_;
            ss[t*50+lane]=e0*r;
            if (lane<17) ss[t*50+lane+32]=e1*r;
        }
        __syncthreads();
        for (int i=tid;i<392;i+=256){
            int t=i>>3, j=i&7;
            float acc=0.f;
            for(int u=0;u<49;u++) acc += ss[t*50+u]*vs[u*68+hh*8+j];
            xsT[(hh*8+j)*64+t]=acc;     // osT
        }
        __syncthreads();
    }
    // proj: osT[c][t] x wp^T
    for (int i=tid;i<4096;i+=256){ int o=i>>6,c=i&63; wT[c*68+o]=wp[o*64+c]; }
    __syncthreads();
    {
        ull a2[4][2];
        #pragma unroll
        for(int i=0;i<4;i++){ a2[i][0]=0ull; a2[i][1]=0ull; }
        for (int c=0;c<64;c++){
            ulonglong2 x2 = *(const ulonglong2*)(xsT + c*64 + t0);
            float4 w4 = *(const float4*)(wT + c*68 + o0);
            ull w0=dup2(w4.x),w1=dup2(w4.y),w2=dup2(w4.z),w3=dup2(w4.w);
            fma2(a2[0][0],w0,x2.x); fma2(a2[0][1],w0,x2.y);
            fma2(a2[1][0],w1,x2.x); fma2(a2[1][1],w1,x2.y);
            fma2(a2[2][0],w2,x2.x); fma2(a2[2][1],w2,x2.y);
            fma2(a2[3][0],w3,x2.x); fma2(a2[3][1],w3,x2.y);
        }
        __syncthreads();   // qs reads (scores) are long done; ensure before overwrite
        #pragma unroll
        for(int i=0;i<4;i++){
            float2 v01=unpk(a2[i][0]), v23=unpk(a2[i][1]);
            qs[(t0+0)*68+o0+i]=v01.x;
            qs[(t0+1)*68+o0+i]=v01.y;
            qs[(t0+2)*68+o0+i]=v23.x;
            qs[(t0+3)*68+o0+i]=v23.y;
        }
    }
    __syncthreads();
    for (int i=tid;i<3136;i+=256){
        int o=i/49, t=i%49;
        g_y[((size_t)b*128+o)*LL + (wy*7+t/7)*56 + wx*7+t%7] = qs[t*68+o] + __ldg(bp+o);
    }
}

// ======== K2a: rms2d + in-proj 64->128 (fma2 4x4 tiles) ========
__global__ void k_rms_in(const float* __restrict__ x, const float* __restrict__ min_w,
                         const float* __restrict__ gvm)
{
    extern __shared__ float sm[];
    float* xt  = sm;            // [64 c][64 p]
    float* ws  = xt + 4096;     // [64 c][132]
    float* inv = ws + 8448;
    int tid = threadIdx.x;
    int b = blockIdx.x / 49, l0 = (blockIdx.x % 49)*64;
    const float* x2p = x + ((size_t)b*128 + 64)*LL;
    for (int i=tid;i<4096;i+=256){ int c=i>>6,p=i&63; xt[i] = x2p[(size_t)c*LL + l0+p]; }
    for (int i=tid;i<8192;i+=256){ int d=i>>6,c=i&63; ws[c*132+d] = min_w[i]*__ldg(gvm+c); }
    __syncthreads();
    if (tid<64){ float v=0.f;
        #pragma unroll 8
        for(int c=0;c<64;c++){float a=xt[c*64+tid]; v+=a*a;}
        inv[tid]=rsqrtf(v*(1.f/64.f)+1e-5f); }
    __syncthreads();
    int p0 = (tid & 15)*4;
    int d0a = (tid>>4)*4, d0b = d0a + 64;
    ull A[2][4][2];
    #pragma unroll
    for(int t=0;t<2;t++)for(int i=0;i<4;i++){A[t][i][0]=0ull;A[t][i][1]=0ull;}
    for (int c=0;c<64;c++){
        ulonglong2 x2 = *(const ulonglong2*)(xt + c*64 + p0);
        float4 wa = *(const float4*)(ws + c*132 + d0a);
        float4 wb2= *(const float4*)(ws + c*132 + d0b);
        ull wA[4]={dup2(wa.x),dup2(wa.y),dup2(wa.z),dup2(wa.w)};
        ull wB[4]={dup2(wb2.x),dup2(wb2.y),dup2(wb2.z),dup2(wb2.w)};
        #pragma unroll
        for(int i=0;i<4;i++){
            fma2(A[0][i][0],wA[i],x2.x); fma2(A[0][i][1],wA[i],x2.y);
            fma2(A[1][i][0],wB[i],x2.x); fma2(A[1][i][1],wB[i],x2.y);
        }
    }
    #pragma unroll
    for(int t=0;t<2;t++){
        int d0 = t? d0b : d0a;
        #pragma unroll
        for(int i=0;i<4;i++){
            float2 u01=unpk(A[t][i][0]), u23=unpk(A[t][i][1]);
            float* dst = g_xin + ((size_t)b*128+d0+i)*LL + l0+p0;
            dst[0]=u01.x*inv[p0+0]; dst[1]=u01.y*inv[p0+1];
            dst[2]=u23.x*inv[p0+2]; dst[3]=u23.y*inv[p0+3];
        }
    }
}

// ======== K2b: depthwise 3x3 + bias + silu ========
__global__ void k_dwconv(const float* __restrict__ cw, const float* __restrict__ cb)
{
    __shared__ float t[58*58];
    int bd = blockIdx.x, d = bd & 127, tid = threadIdx.x;
    const float* src = g_xin + (size_t)bd*LL;
    for (int i=tid;i<58*58;i+=256){
        int hh = i/58 - 1, ww = i%58 - 1;
        t[i] = (hh>=0 && hh<56 && ww>=0 && ww<56) ? src[hh*56+ww] : 0.f;
    }
    float w9[9];
    #pragma unroll
    for(int j=0;j<9;j++) w9[j] = cw[d*9+j];
    float bias = cb[d];
    __syncthreads();
    float* dst = g_xconv + (size_t)bd*LL;
    for (int i=tid;i<LL;i+=256){
        const float* tp = t + (i/56)*58 + i%56;
        float a = bias;
        #pragma unroll
        for(int dy=0;dy<3;dy++)
            #pragma unroll
            for(int dx=0;dx<3;dx++) a += w9[dy*3+dx]*tp[dy*58+dx];
        dst[i] = a / (1.f + __expf(-a));
    }
}

// ======== K2c: per-plane transpose ========
__global__ void k_transpose(){
    __shared__ float t[56*57];
    int bd = blockIdx.x, tid = threadIdx.x;
    const float* src = g_xconv + (size_t)bd*LL;
    float* dst = g_xconvT + (size_t)bd*LL;
    for(int i=tid;i<LL;i+=256) t[(i/56)*57 + i%56] = src[i];
    __syncthreads();
    for(int j=tid;j<LL;j+=256) dst[j] = t[(j%56)*57 + j/56];
}

// ======== K3: xproj + dt + softplus -> (delta,du) packed + B/C ========
__global__ void k_xproj(const float* __restrict__ xproj, const float* __restrict__ dtw,
                        const float* __restrict__ dtb)
{
    extern __shared__ float sm[];
    float* xt    = sm;              // [128 d][64 p]
    float* wp_   = xt + 8192;       // [128 d][36 c]
    float* xd    = wp_ + 4608;      // [36][65]
    float* dtw_s = xd + 2340;
    float* dtb_s = dtw_s + 512;
    int tid = threadIdx.x, blk = blockIdx.x;
    int b = blk / 196, r = blk % 196, k = r / 49, l0 = (r%49)*64;
    const float* src = ((k&1)? g_xconvT : g_xconv) + (size_t)b*128*LL;
    bool rev = k >= 2;
    for (int i=tid;i<8192;i+=256){
        int d=i>>6,p=i&63;
        int pos = rev ? (LL-1-(l0+p)) : (l0+p);
        xt[i] = src[(size_t)d*LL + pos];
    }
    for (int i=tid;i<4608;i+=256) wp_[i] = xproj[(size_t)k*4608 + i];
    for (int i=tid;i<512;i+=256) dtw_s[i] = dtw[k*512+i];
    if (tid<128) dtb_s[tid] = dtb[k*128+tid];
    __syncthreads();
    if (tid < 144){
        int c0 = (tid>>4)*4, p0 = (tid&15)*4;
        ull A[4][2];
        #pragma unroll
        for(int i=0;i<4;i++){A[i][0]=0ull;A[i][1]=0ull;}
        for (int d=0;d<128;d++){
            float4 w4 = *(const float4*)(wp_ + d*36 + c0);
            ulonglong2 x2 = *(const ulonglong2*)(xt + d*64 + p0);
            ull w0=dup2(w4.x),w1=dup2(w4.y),w2=dup2(w4.z),w3=dup2(w4.w);
            fma2(A[0][0],w0,x2.x); fma2(A[0][1],w0,x2.y);
            fma2(A[1][0],w1,x2.x); fma2(A[1][1],w1,x2.y);
            fma2(A[2][0],w2,x2.x); fma2(A[2][1],w2,x2.y);
            fma2(A[3][0],w3,x2.x); fma2(A[3][1],w3,x2.y);
        }
        #pragma unroll
        for(int i=0;i<4;i++){
            float2 v01=unpk(A[i][0]), v23=unpk(A[i][1]);
            xd[(c0+i)*65+p0+0]=v01.x; xd[(c0+i)*65+p0+1]=v01.y;
            xd[(c0+i)*65+p0+2]=v23.x; xd[(c0+i)*65+p0+3]=v23.y;
        }
    }
    __syncthreads();
    size_t ddbase = ((size_t)(b*4+k)*LL)*128;
    for (int i=tid;i<8192;i+=256){
        int d=i>>6, p=i&63;
        float a = dtb_s[d];
        #pragma unroll
        for(int rr=0;rr<4;rr++) a += xd[rr*65+p]*dtw_s[d*4+rr];
        float sp = (a > 15.f) ? a : __logf(1.f + __expf(a));
        g_dd[ddbase + (size_t)(l0+p)*128 + d] = make_float2(sp, sp*xt[d*64+p]);
    }
    size_t bcbase = ((size_t)(b*4+k)*LL + l0)*16;
    for (int i=tid;i<1024;i+=256){
        int p = i>>4, n = i&15;
        g_Bc[bcbase + (size_t)p*16 + n] = xd[(4+n)*65+p];
        g_Cc[bcbase + (size_t)p*16 + n] = xd[(20+n)*65+p];
    }
}

// ======== K4: chunked selective scan (coalesced dd loads) ========
__global__ void __launch_bounds__(128) k_scan1(const float* __restrict__ Alog)
{
    int blk = blockIdx.x;                 // 2048
    int ch = blk & 15, sb = blk >> 4;
    int b = sb >> 3, k = (sb>>1)&3, half = sb&1;
    int wid = threadIdx.x >> 5, lane = threadIdx.x & 31;
    int s = lane >> 1, sub = lane & 1;
    int d = half*64 + wid*16 + s;
    size_t seq = (size_t)(b*4+k)*128 + d;
    const float2* ddp = g_dd + (size_t)(b*4+k)*LL*128;
    float A[8];
    #pragma unroll
    for(int j=0;j<8;j++) A[j] = -__expf(__ldg(Alog + ((size_t)k*128+d)*16 + sub*8 + j));
    const float4* B4 = (const float4*)(g_Bc + (size_t)(b*4+k)*LL*16) + sub*2;
    float h0=0,h1=0,h2=0,h3=0,h4=0,h5=0,h6=0,h7=0, sdl=0.f;
    int t0 = ch*CL;
    for (int tt=0;tt<CL;tt++){
        int t = t0+tt;
        float2 dd = __ldg(ddp + (size_t)t*128 + d);
        float dl = dd.x, du = dd.y;
        float4 ba = __ldg(B4 + (size_t)t*4);
        float4 bb = __ldg(B4 + (size_t)t*4 + 1);
        h0 = __expf(dl*A[0])*h0 + du*ba.x;
        h1 = __expf(dl*A[1])*h1 + du*ba.y;
        h2 = __expf(dl*A[2])*h2 + du*ba.z;
        h3 = __expf(dl*A[3])*h3 + du*ba.w;
        h4 = __expf(dl*A[4])*h4 + du*bb.x;
        h5 = __expf(dl*A[5])*h5 + du*bb.y;
        h6 = __expf(dl*A[6])*h6 + du*bb.z;
        h7 = __expf(dl*A[7])*h7 + du*bb.w;
        sdl += dl;
    }
    size_t base = seq*256 + ch*16 + sub*8;
    g_hend[base+0]=h0; g_hend[base+1]=h1; g_hend[base+2]=h2; g_hend[base+3]=h3;
    g_hend[base+4]=h4; g_hend[base+5]=h5; g_hend[base+6]=h6; g_hend[base+7]=h7;
    if (sub==0) g_sdl[seq*16+ch] = sdl;
}
__global__ void k_fix(const float* __restrict__ Alog)
{
    int idx = blockIdx.x*256 + threadIdx.x;   // 131072
    int seq = idx >> 4, st = idx & 15;
    int k = (seq>>7)&3, d = seq&127;
    float A = -__expf(__ldg(Alog + ((size_t)k*128+d)*16 + st));
    float h = 0.f;
    #pragma unroll
    for (int c=0;c<CH;c++){
        size_t o = (size_t)seq*256 + c*16 + st;
        float he = g_hend[o];
        g_hend[o] = h;
        h = __expf(A*g_sdl[seq*16+c])*h + he;
    }
}
__global__ void __launch_bounds__(128) k_scan2(const float* __restrict__ Alog)
{
    int blk = blockIdx.x;
    int ch = blk & 15, sb = blk >> 4;
    int b = sb >> 3, k = (sb>>1)&3, half = sb&1;
    int wid = threadIdx.x >> 5, lane = threadIdx.x & 31;
    int s = lane >> 1, sub = lane & 1;
    int d = half*64 + wid*16 + s;
    size_t seq = (size_t)(b*4+k)*128 + d;
    const float2* ddp = g_dd + (size_t)(b*4+k)*LL*128;
    float* yptr = g_ys + seq*LL;
    bool rev = k>=2;
    float A[8];
    #pragma unroll
    for(int j=0;j<8;j++) A[j] = -__expf(__ldg(Alog + ((size_t)k*128+d)*16 + sub*8 + j));
    const float4* B4 = (const float4*)(g_Bc + (size_t)(b*4+k)*LL*16) + sub*2;
    const float4* C4 = (const float4*)(g_Cc + (size_t)(b*4+k)*LL*16) + sub*2;
    size_t base = seq*256 + ch*16 + sub*8;
    float h0=g_hend[base+0],h1=g_hend[base+1],h2=g_hend[base+2],h3=g_hend[base+3];
    float h4=g_hend[base+4],h5=g_hend[base+5],h6=g_hend[base+6],h7=g_hend[base+7];
    int t0 = ch*CL;
    for (int tt=0;tt<CL;tt++){
        int t = t0+tt;
        float2 dd = __ldg(ddp + (size_t)t*128 + d);
        float dl = dd.x, du = dd.y;
        float4 ba = __ldg(B4 + (size_t)t*4);
        float4 bb = __ldg(B4 + (size_t)t*4 + 1);
        float4 ca = __ldg(C4 + (size_t)t*4);
        float4 cb = __ldg(C4 + (size_t)t*4 + 1);
        float y;
        h0 = __expf(dl*A[0])*h0 + du*ba.x; y  = h0*ca.x;
        h1 = __expf(dl*A[1])*h1 + du*ba.y; y += h1*ca.y;
        h2 = __expf(dl*A[2])*h2 + du*ba.z; y += h2*ca.z;
        h3 = __expf(dl*A[3])*h3 + du*ba.w; y += h3*ca.w;
        h4 = __expf(dl*A[4])*h4 + du*bb.x; y += h4*cb.x;
        h5 = __expf(dl*A[5])*h5 + du*bb.y; y += h5*cb.y;
        h6 = __expf(dl*A[6])*h6 + du*bb.z; y += h6*cb.z;
        h7 = __expf(dl*A[7])*h7 + du*bb.w; y += h7*cb.w;
        y += __shfl_xor_sync(0xffffffffu, y, 1);
        if (sub == 0){
            int pos = rev ? (LL-1-t) : t;
            yptr[pos] = y;
        }
    }
}

// ======== K4b: cross-merge + D-term + gelu ========
__global__ void k_merge(const float* __restrict__ Dp){
    __shared__ float t[56*57];
    int bd = blockIdx.x, b = bd >> 7, d = bd & 127, tid = threadIdx.x;
    size_t base = ((size_t)b*4)*128*LL + (size_t)d*LL;
    const float* y0 = g_ys + base;
    const float* y1 = g_ys + base + (size_t)128*LL;
    const float* y2 = g_ys + base + (size_t)2*128*LL;
    const float* y3 = g_ys + base + (size_t)3*128*LL;
    float D02 = __ldg(Dp+d) + __ldg(Dp+256+d);
    float D13 = __ldg(Dp+128+d) + __ldg(Dp+384+d);
    const float* xc  = g_xconv  + ((size_t)b*128+d)*LL;
    const float* xcT = g_xconvT + ((size_t)b*128+d)*LL;
    for (int j=tid;j<LL;j+=256) t[(j/56)*57 + j%56] = y1[j] + y3[j] + D13*xcT[j];
    __syncthreads();
    float* dst = g_yg + ((size_t)b*128 + d)*LL;
    for (int i=tid;i<LL;i+=256){
        float v = y0[i] + y2[i] + D02*xc[i] + t[(i%56)*57 + i/56];
        dst[i] = gelu_t(v);
    }
}

// ======== K5: out-proj 128->64 (fma2 4x4 tiles) ========
__global__ void k_outproj(const float* __restrict__ ow){
    extern __shared__ float sm[];
    float* ws = sm;            // [128 d][68]
    float* yt = ws + 8704;     // [128 d][64 p]
    int tid=threadIdx.x;
    int b = blockIdx.x/49, l0=(blockIdx.x%49)*64;
    for (int i=tid;i<8192;i+=256){ int o=i>>7, d=i&127; ws[d*68+o]=ow[i]; }
    const float* src = g_yg + (size_t)b*128*LL;
    for (int i=tid;i<8192;i+=256){ int d=i>>6,p=i&63; yt[i]=src[(size_t)d*LL+l0+p]; }
    __syncthreads();
    int o0=(tid>>4)*4, p0=(tid&15)*4;
    ull A[4][2];
    #pragma unroll
    for(int i=0;i<4;i++){A[i][0]=0ull;A[i][1]=0ull;}
    for (int d=0;d<128;d++){
        float4 w4 = *(const float4*)(ws + d*68 + o0);
        ulonglong2 x2 = *(const ulonglong2*)(yt + d*64 + p0);
        ull w0=dup2(w4.x),w1=dup2(w4.y),w2=dup2(w4.z),w3=dup2(w4.w);
        fma2(A[0][0],w0,x2.x); fma2(A[0][1],w0,x2.y);
        fma2(A[1][0],w1,x2.x); fma2(A[1][1],w1,x2.y);
        fma2(A[2][0],w2,x2.x); fma2(A[2][1],w2,x2.y);
        fma2(A[3][0],w3,x2.x); fma2(A[3][1],w3,x2.y);
    }
    #pragma unroll
    for(int i=0;i<4;i++){
        float2 v01=unpk(A[i][0]), v23=unpk(A[i][1]);
        float* dst = g_y + ((size_t)b*128 + 64 + o0+i)*LL + l0+p0;
        dst[0]=v01.x; dst[1]=v01.y; dst[2]=v23.x; dst[3]=v23.y;
    }
}

// ======== K6: SE pool / gate / residual ========
__global__ void k_pool(){
    __shared__ float red[256];
    int bc = blockIdx.x, tid = threadIdx.x;
    const float* src = g_y + (size_t)bc*LL;
    float s=0.f;
    for(int i=tid;i<LL;i+=256) s += src[i];
    red[tid]=s; __syncthreads();
    for(int o=128;o>0;o>>=1){ if(tid<o) red[tid]+=red[tid+o]; __syncthreads(); }
    if(tid==0) g_p[bc] = red[0]*(1.f/LL);
}
__global__ void k_se(const float* __restrict__ w1, const float* __restrict__ b1,
                     const float* __restrict__ w2, const float* __restrict__ b2){
    __shared__ float p[128], hid[32];
    int b = blockIdx.x, tid = threadIdx.x;
    if (tid<128) p[tid] = g_p[b*128+tid];
    __syncthreads();
    if (tid<32){
        float a = b1[tid];
        #pragma unroll 8
        for(int c=0;c<128;c++) a += w1[tid*128+c]*p[c];
        hid[tid] = fmaxf(a, 0.f);
    }
    __syncthreads();
    if (tid<128){
        float a = b2[tid];
        #pragma unroll
        for(int j=0;j<32;j++) a += w2[tid*32+j]*hid[j];
        g_s[b*128+tid] = 1.f/(1.f+__expf(-a));
    }
}
__global__ void k_resid(const float* __restrict__ x, const float* __restrict__ gamma1){
    size_t i = (size_t)blockIdx.x*256 + threadIdx.x;
    if (i >= (size_t)NB*128*LL) return;
    int bc = (int)(i / LL);
    int c = bc & 127;
    g_xres[i] = x[i] + gamma1[c]*g_s[bc]*g_y[i];
}

// ======== K7: fused RMS + MLP(128->512->128) + residual (fma2) ========
__global__ void __launch_bounds__(256) k_mlp(
    const float* __restrict__ gmlp,
    const float* __restrict__ w1, const float* __restrict__ b1,
    const float* __restrict__ w2, const float* __restrict__ b2,
    const float* __restrict__ gamma2, float* __restrict__ out)
{
    extern __shared__ float sm[];
    float* xt   = sm;            // [128 c][64 p]
    float* h    = xt + 8192;     // [64 j][68 p]
    float* wc   = h + 4352;      // pass1 [128 c][68 j]; pass2 [64 j][132 o]
    float* invp = wc + 8704;     // 64
    int tid = threadIdx.x;
    int b = blockIdx.x/49, l0 = (blockIdx.x%49)*64;
    const float* src = g_xres + (size_t)b*128*LL;
    for (int i=tid;i<8192;i+=256){ int c=i>>6,p=i&63; xt[i] = src[(size_t)c*LL + l0+p]; }
    __syncthreads();
    if (tid < 64){
        float v=0.f;
        #pragma unroll 8
        for(int c=0;c<128;c++){ float a=xt[c*64+tid]; v+=a*a; }
        invp[tid] = rsqrtf(v*(1.f/128.f)+1e-5f);
    }
    __syncthreads();
    int o0 = (tid>>4)*8, p0q = (tid&15)*4;
    ull acc2[4][4];
    #pragma unroll
    for(int i=0;i<4;i++)for(int q=0;q<4;q++) acc2[i][q]=0ull;
    int j0 = (tid&15)*4, p1 = (tid>>4)*4;
    for (int cc=0; cc<8; cc++){
        for (int i=tid;i<2048;i+=256){
            int j = i>>5, c0 = (i&31)*4;
            float4 wv = *(const float4*)(w1 + (size_t)(cc*64+j)*128 + c0);
            wc[(c0+0)*68+j] = wv.x*__ldg(gmlp+c0+0);
            wc[(c0+1)*68+j] = wv.y*__ldg(gmlp+c0+1);
            wc[(c0+2)*68+j] = wv.z*__ldg(gmlp+c0+2);
            wc[(c0+3)*68+j] = wv.w*__ldg(gmlp+c0+3);
        }
        __syncthreads();
        {
            ull A[4][2];
            #pragma unroll
            for(int i=0;i<4;i++){A[i][0]=0ull;A[i][1]=0ull;}
            for (int c=0;c<128;c++){
                float4 w4 = *(const float4*)(wc + c*68 + j0);
                ulonglong2 x2 = *(const ulonglong2*)(xt + c*64 + p1);
                ull w0=dup2(w4.x),w1p=dup2(w4.y),w2p=dup2(w4.z),w3p=dup2(w4.w);
                fma2(A[0][0],w0,x2.x);  fma2(A[0][1],w0,x2.y);
                fma2(A[1][0],w1p,x2.x); fma2(A[1][1],w1p,x2.y);
                fma2(A[2][0],w2p,x2.x); fma2(A[2][1],w2p,x2.y);
                fma2(A[3][0],w3p,x2.x); fma2(A[3][1],w3p,x2.y);
            }
            #pragma unroll
            for(int i=0;i<4;i++){
                float bb = b1[cc*64+j0+i];
                float2 v01=unpk(A[i][0]), v23=unpk(A[i][1]);
                h[(j0+i)*68+p1+0] = gelu_t(v01.x*invp[p1+0] + bb);
                h[(j0+i)*68+p1+1] = gelu_t(v01.y*invp[p1+1] + bb);
                h[(j0+i)*68+p1+2] = gelu_t(v23.x*invp[p1+2] + bb);
                h[(j0+i)*68+p1+3] = gelu_t(v23.y*invp[p1+3] + bb);
            }
        }
        __syncthreads();
        for (int i=tid;i<8192;i+=256){
            int j=i&63, o=i>>6;
            wc[j*132+o] = w2[(size_t)o*512 + cc*64 + j];
        }
        __syncthreads();
        for (int j=0;j<64;j++){
            ulonglong2 wlo = *(const ulonglong2*)(wc + j*132 + o0);
            ulonglong2 whi = *(const ulonglong2*)(wc + j*132 + o0 + 4);
            float4 hv = *(const float4*)(h + j*68 + p0q);
            ull h0=dup2(hv.x), h1=dup2(hv.y), h2=dup2(hv.z), h3=dup2(hv.w);
            fma2(acc2[0][0],wlo.x,h0); fma2(acc2[0][1],wlo.x,h1); fma2(acc2[0][2],wlo.x,h2); fma2(acc2[0][3],wlo.x,h3);
            fma2(acc2[1][0],wlo.y,h0); fma2(acc2[1][1],wlo.y,h1); fma2(acc2[1][2],wlo.y,h2); fma2(acc2[1][3],wlo.y,h3);
            fma2(acc2[2][0],whi.x,h0); fma2(acc2[2][1],whi.x,h1); fma2(acc2[2][2],whi.x,h2); fma2(acc2[2][3],whi.x,h3);
            fma2(acc2[3][0],whi.y,h0); fma2(acc2[3][1],whi.y,h1); fma2(acc2[3][2],whi.y,h2); fma2(acc2[3][3],whi.y,h3);
        }
        __syncthreads();
    }
    #pragma unroll
    for(int i=0;i<4;i++){
        int oa = o0 + 2*i, ob = oa + 1;
        float ga = gamma2[oa], ba = b2[oa];
        float gb = gamma2[ob], bbv = b2[ob];
        #pragma unroll
        for(int q=0;q<4;q++){
            int p = p0q+q;
            float2 v = unpk(acc2[i][q]);
            out[((size_t)b*128+oa)*LL + l0 + p] = xt[oa*64+p] + ga*(v.x + ba);
            out[((size_t)b*128+ob)*LL + l0 + p] = xt[ob*64+p] + gb*(v.y + bbv);
        }
    }
}

// ======== launch ========
extern "C" void kernel_launch(void* const* d_in, const int* in_sizes, int n_in,
                              void* d_out, int out_size) {
    const float* x      = (const float*)d_in[0];
    const float* wq     = (const float*)d_in[1];
    const float* wk     = (const float*)d_in[2];
    const float* wv     = (const float*)d_in[3];
    const float* w_proj = (const float*)d_in[4];
    const float* b_proj = (const float*)d_in[5];
    const float* g_q    = (const float*)d_in[6];
    const float* g_k    = (const float*)d_in[7];
    const float* g_v    = (const float*)d_in[8];
    const float* g_vm   = (const float*)d_in[9];
    const float* g_mlp  = (const float*)d_in[10];
    const float* m_in_w = (const float*)d_in[11];
    const float* m_conv_w=(const float*)d_in[12];
    const float* m_conv_b=(const float*)d_in[13];
    const float* m_xproj=(const float*)d_in[14];
    const float* m_dtw  = (const float*)d_in[15];
    const float* m_dtb  = (const float*)d_in[16];
    const float* m_Alog = (const float*)d_in[17];
    const float* m_D    = (const float*)d_in[18];
    const float* m_out_w= (const float*)d_in[19];
    const float* se_w1  = (const float*)d_in[20];
    const float* se_b1  = (const float*)d_in[21];
    const float* se_w2  = (const float*)d_in[22];
    const float* se_b2  = (const float*)d_in[23];
    const float* mlp_w1 = (const float*)d_in[24];
    const float* mlp_b1 = (const float*)d_in[25];
    const float* mlp_w2 = (const float*)d_in[26];
    const float* mlp_b2 = (const float*)d_in[27];
    const float* gamma1 = (const float*)d_in[28];
    const float* gamma2 = (const float*)d_in[29];
    float* out = (float*)d_out;

    static bool attr_done = false;
    if (!attr_done){
        cudaFuncSetAttribute(k_attn,    cudaFuncAttributeMaxDynamicSharedMemorySize, 96512);
        cudaFuncSetAttribute(k_rms_in,  cudaFuncAttributeMaxDynamicSharedMemorySize, 50432);
        cudaFuncSetAttribute(k_xproj,   cudaFuncAttributeMaxDynamicSharedMemorySize, 63200);
        cudaFuncSetAttribute(k_outproj, cudaFuncAttributeMaxDynamicSharedMemorySize, 67584);
        cudaFuncSetAttribute(k_mlp,     cudaFuncAttributeMaxDynamicSharedMemorySize, 85504);
        attr_done = true;
    }

    k_attn<<<1024, 256, 96128>>>(x, wq, wk, wv, w_proj, b_proj, g_q, g_k, g_v);
    k_rms_in<<<16*49, 256, 50432>>>(x, m_in_w, g_vm);
    k_dwconv<<<16*128, 256>>>(m_conv_w, m_conv_b);
    k_transpose<<<16*128, 256>>>();
    k_xproj<<<16*196, 256, 63120>>>(m_xproj, m_dtw, m_dtb);
    k_scan1<<<2048, 128>>>(m_Alog);
    k_fix<<<512, 256>>>(m_Alog);
    k_scan2<<<2048, 128>>>(m_Alog);
    k_merge<<<16*128, 256>>>(m_D);
    k_outproj<<<16*49, 256, 67584>>>(m_out_w);
    k_pool<<<2048, 256>>>();
    k_se<<<16, 128>>>(se_w1, se_b1, se_w2, se_b2);
    {
        size_t N = (size_t)NB*128*LL;
        k_resid<<<(unsigned)((N + 255)/256), 256>>>(x, gamma1);
    }
    k_mlp<<<16*49, 256, 85248>>>(g_mlp, mlp_w1, mlp_b1, mlp_w2, mlp_b2, gamma2, out);
}